// round 8
// baseline (speedup 1.0000x reference)
#include <cuda_runtime.h>
#include <cstdint>

// LIF forward: X[B=128, T=32, N=8192] fp32 -> spikes fp32.
// R8: phase-separated traffic. Spikes are binary, so each thread packs its
// full output (4 columns x 32 timesteps) into 4 uint32 bitmasks during a
// pure-READ phase (32 loads + recurrence, zero stores), then expands and
// writes all 32 planes in a pure-WRITE phase. This removes the fine-grained
// read/write interleave that forces continuous DRAM bus turnaround in
// R1-R7 (all pinned at ~7.0 TB/s effective of the 8 TB/s spec).

static constexpr int B = 128;
static constexpr int T = 32;
static constexpr int N = 8192;
static constexpr int N4 = N / 4;          // 2048 float4 columns
static constexpr int TOTAL4 = B * N4;     // 262144 float4 lanes
static constexpr int TPB = 256;

__global__ __launch_bounds__(TPB) void lif_kernel(const float4* __restrict__ X,
                                                  float4* __restrict__ out) {
    int idx = blockIdx.x * TPB + threadIdx.x;  // 0 .. TOTAL4-1

    int b = idx / N4;
    int n4 = idx - b * N4;

    const float4* xp = X + (size_t)b * T * N4 + n4;
    float4* op = out + (size_t)b * T * N4 + n4;

    float4 m = make_float4(0.f, 0.f, 0.f, 0.f);
    uint32_t b0 = 0, b1 = 0, b2 = 0, b3 = 0;  // spike bitmasks, bit t = plane t

    // ---- Phase 1: pure read + recurrence, spikes packed to bits ----
#pragma unroll
    for (int t = 0; t < T; t++) {
        float4 x = xp[(size_t)t * N4];

        m.x = m.x + (x.x - m.x) * 0.5f;
        m.y = m.y + (x.y - m.y) * 0.5f;
        m.z = m.z + (x.z - m.z) * 0.5f;
        m.w = m.w + (x.w - m.w) * 0.5f;

        uint32_t s0 = (m.x > 1.0f) ? 1u : 0u;
        uint32_t s1 = (m.y > 1.0f) ? 1u : 0u;
        uint32_t s2 = (m.z > 1.0f) ? 1u : 0u;
        uint32_t s3 = (m.w > 1.0f) ? 1u : 0u;

        b0 |= s0 << t;
        b1 |= s1 << t;
        b2 |= s2 << t;
        b3 |= s3 << t;

        if (s0) m.x = 0.0f;
        if (s1) m.y = 0.0f;
        if (s2) m.z = 0.0f;
        if (s3) m.w = 0.0f;
    }

    // ---- Phase 2: pure write, expand bits to fp32 spikes ----
#pragma unroll
    for (int t = 0; t < T; t++) {
        float4 s;
        s.x = ((b0 >> t) & 1u) ? 1.0f : 0.0f;
        s.y = ((b1 >> t) & 1u) ? 1.0f : 0.0f;
        s.z = ((b2 >> t) & 1u) ? 1.0f : 0.0f;
        s.w = ((b3 >> t) & 1u) ? 1.0f : 0.0f;
        op[(size_t)t * N4] = s;
    }
}

extern "C" void kernel_launch(void* const* d_in, const int* in_sizes, int n_in,
                              void* d_out, int out_size) {
    const float4* X = (const float4*)d_in[0];
    float4* out = (float4*)d_out;
    lif_kernel<<<TOTAL4 / TPB, TPB>>>(X, out);
}